// round 14
// baseline (speedup 1.0000x reference)
#include <cuda_runtime.h>
#include <cstdint>

#define CC     64
#define NCOMP  13
#define NPATHS 11
#define RR     8
#define HH     64
#define MAXN   8000
#define MAXE   256000
#define WCOLS  (NPATHS * CC)   // 704

__device__ __align__(16) float g_u[MAXN * NCOMP * CC];
__device__ __align__(16) float g_acc[MAXN * NCOMP * CC];
__device__ __align__(16) float g_h[MAXE * HH];
// fragment-order tf32 weights: [(col*4 + tig)*16 + ks*2 + {b0,b1}]
__device__ __align__(16) float g_wr3t[WCOLS * 4 * 16];
__device__ __align__(16) float g_wr0t[HH * 4 * 2];
__device__ __align__(16) float g_wr1t[HH * 4 * 16];
__device__ __align__(16) float g_wr2t[HH * 4 * 16];

typedef unsigned long long u64t;

__device__ __forceinline__ u64t pack2(float lo, float hi) {
    u64t r; asm("mov.b64 %0,{%1,%2};" : "=l"(r) : "f"(lo), "f"(hi)); return r;
}
__device__ __forceinline__ void unpack2(u64t v, float& lo, float& hi) {
    asm("mov.b64 {%0,%1},%2;" : "=f"(lo), "=f"(hi) : "l"(v));
}
__device__ __forceinline__ u64t fma2(u64t a, u64t b, u64t c) {
    u64t d; asm("fma.rn.f32x2 %0,%1,%2,%3;" : "=l"(d) : "l"(a), "l"(b), "l"(c)); return d;
}
__device__ __forceinline__ void red4(float* p, float x, float y, float z, float w) {
    asm volatile("red.global.add.v4.f32 [%0], {%1,%2,%3,%4};"
                 :: "l"(p), "f"(x), "f"(y), "f"(z), "f"(w) : "memory");
}
__device__ __forceinline__ float silu(float x) { return x / (1.0f + __expf(-x)); }
__device__ __forceinline__ float cvt_tf32(float x) {
    uint32_t u; asm("cvt.rna.tf32.f32 %0, %1;" : "=r"(u) : "f"(x));
    return __uint_as_float(u);
}
__device__ __forceinline__ void mma_tf32(float& d0, float& d1, float& d2, float& d3,
                                         uint32_t a0, uint32_t a1, uint32_t a2, uint32_t a3,
                                         uint32_t b0, uint32_t b1) {
    asm volatile("mma.sync.aligned.m16n8k8.row.col.f32.tf32.tf32.f32 "
                 "{%0,%1,%2,%3}, {%4,%5,%6,%7}, {%8,%9}, {%0,%1,%2,%3};"
                 : "+f"(d0), "+f"(d1), "+f"(d2), "+f"(d3)
                 : "r"(a0), "r"(a1), "r"(a2), "r"(a3), "r"(b0), "r"(b1));
}

// ---------------------------------------------------------------------------
__global__ void k_prep(const float* __restrict__ Wr0, const float* __restrict__ Wr1,
                       const float* __restrict__ Wr2, const float* __restrict__ Wr3,
                       int n4) {
    int i = blockIdx.x * blockDim.x + threadIdx.x;
    if (i < n4) reinterpret_cast<float4*>(g_acc)[i] = make_float4(0.f, 0.f, 0.f, 0.f);
    if (i < 22528) {
        int c = i >> 5, t = (i >> 3) & 3, ks = i & 7;
        g_wr3t[((c * 4 + t) << 4) + ks * 2]     = cvt_tf32(Wr3[(ks * 8 + t) * WCOLS + c]);
        g_wr3t[((c * 4 + t) << 4) + ks * 2 + 1] = cvt_tf32(Wr3[(ks * 8 + t + 4) * WCOLS + c]);
    } else if (i < 22528 + 2048) {
        int j = i - 22528;
        int c = j >> 5, t = (j >> 3) & 3, ks = j & 7;
        g_wr1t[((c * 4 + t) << 4) + ks * 2]     = cvt_tf32(Wr1[(ks * 8 + t) * HH + c]);
        g_wr1t[((c * 4 + t) << 4) + ks * 2 + 1] = cvt_tf32(Wr1[(ks * 8 + t + 4) * HH + c]);
    } else if (i < 22528 + 4096) {
        int j = i - 22528 - 2048;
        int c = j >> 5, t = (j >> 3) & 3, ks = j & 7;
        g_wr2t[((c * 4 + t) << 4) + ks * 2]     = cvt_tf32(Wr2[(ks * 8 + t) * HH + c]);
        g_wr2t[((c * 4 + t) << 4) + ks * 2 + 1] = cvt_tf32(Wr2[(ks * 8 + t + 4) * HH + c]);
    } else if (i < 22528 + 4096 + 256) {
        int j = i - 22528 - 4096;
        int c = j >> 2, t = j & 3;
        g_wr0t[j * 2]     = cvt_tf32(Wr0[t * HH + c]);
        g_wr0t[j * 2 + 1] = cvt_tf32(Wr0[(t + 4) * HH + c]);
    }
}

// ---------------------------------------------------------------------------
__global__ void __launch_bounds__(128) k_linear_up(
    const float* __restrict__ t0, const float* __restrict__ t1, const float* __restrict__ t2,
    const float* __restrict__ W0, const float* __restrict__ W1, const float* __restrict__ W2)
{
    __shared__ float s_t[NCOMP][CC];
    const int n = blockIdx.x, tid = threadIdx.x;
    for (int idx = tid; idx < NCOMP * CC; idx += 128) {
        int comp = idx >> 6, c = idx & 63;
        float v;
        if (comp == 0)      v = t0[n * CC + c];
        else if (comp < 4)  v = t1[(n * CC + c) * 3 + (comp - 1)];
        else                v = t2[(n * CC + c) * 9 + (comp - 4)];
        s_t[comp][c] = v;
    }
    __syncthreads();
    for (int pr = tid; pr < NCOMP * 32; pr += 128) {
        int comp = pr >> 5, dp = (pr & 31) * 2;
        const float* __restrict__ W = (comp == 0) ? W0 : ((comp < 4) ? W1 : W2);
        u64t acc = 0ull;
        #pragma unroll 8
        for (int c = 0; c < CC; c++) {
            float s = s_t[comp][c];
            acc = fma2(*(const u64t*)&W[c * CC + dp], pack2(s, s), acc);
        }
        float lo, hi; unpack2(acc, lo, hi);
        float* o = &g_u[(n * NCOMP + comp) * CC + dp];
        o[0] = lo; o[1] = hi;
    }
}

// ---------------------------------------------------------------------------
// Tensor-core radial MLP (unchanged from round 11)
#define MEPB 128
#define MHP  68
#define M_SMEM ((1024 + MEPB * MHP) * 4)

__global__ void __launch_bounds__(256, 4) k_mlp(const float* __restrict__ ef, int E)
{
    extern __shared__ float sm[];
    float* s_f = sm;
    float* s_h = sm + 1024;

    const int tid  = threadIdx.x;
    const int e0   = blockIdx.x * MEPB;
    const int lane = tid & 31;
    const int wid  = tid >> 5;
    const int gid  = lane >> 2, tig = lane & 3;
    const int ra   = wid * 16 + gid, rb = ra + 8;

    {
        int row = tid >> 1, q = (tid & 1) * 4;
        int ge = e0 + row; if (ge >= E) ge = E - 1;
        float4 v = *(const float4*)&ef[ge * RR + q];
        v.x = cvt_tf32(v.x); v.y = cvt_tf32(v.y); v.z = cvt_tf32(v.z); v.w = cvt_tf32(v.w);
        *(float4*)&s_f[row * RR + q] = v;
    }
    __syncwarp();

    const uint32_t* fA = (const uint32_t*)s_f;
    const uint32_t* hA = (const uint32_t*)s_h;

    {
        uint32_t a0 = fA[ra * RR + tig], a1 = fA[rb * RR + tig];
        uint32_t a2 = fA[ra * RR + tig + 4], a3 = fA[rb * RR + tig + 4];
        #pragma unroll
        for (int nt = 0; nt < 8; nt++) {
            const int nb = nt * 8 + gid;
            float2 b = *(const float2*)&g_wr0t[(nb * 4 + tig) * 2];
            float d0 = 0.f, d1 = 0.f, d2 = 0.f, d3 = 0.f;
            mma_tf32(d0, d1, d2, d3, a0, a1, a2, a3,
                     __float_as_uint(b.x), __float_as_uint(b.y));
            const int c = nt * 8 + tig * 2;
            s_h[ra * MHP + c]     = cvt_tf32(silu(d0));
            s_h[ra * MHP + c + 1] = cvt_tf32(silu(d1));
            s_h[rb * MHP + c]     = cvt_tf32(silu(d2));
            s_h[rb * MHP + c + 1] = cvt_tf32(silu(d3));
        }
    }
    __syncwarp();

    {
        uint32_t a[8][4];
        #pragma unroll
        for (int ks = 0; ks < 8; ks++) {
            a[ks][0] = hA[ra * MHP + ks * 8 + tig];
            a[ks][1] = hA[rb * MHP + ks * 8 + tig];
            a[ks][2] = hA[ra * MHP + ks * 8 + tig + 4];
            a[ks][3] = hA[rb * MHP + ks * 8 + tig + 4];
        }
        __syncwarp();
        #pragma unroll
        for (int nt = 0; nt < 8; nt++) {
            const int nb = nt * 8 + gid;
            const float4* bp = (const float4*)&g_wr1t[(nb * 4 + tig) << 4];
            float4 q0 = __ldg(bp), q1 = __ldg(bp + 1), q2 = __ldg(bp + 2), q3 = __ldg(bp + 3);
            float bv[16] = {q0.x,q0.y,q0.z,q0.w, q1.x,q1.y,q1.z,q1.w,
                            q2.x,q2.y,q2.z,q2.w, q3.x,q3.y,q3.z,q3.w};
            float d0 = 0.f, d1 = 0.f, d2 = 0.f, d3 = 0.f;
            #pragma unroll
            for (int ks = 0; ks < 8; ks++)
                mma_tf32(d0, d1, d2, d3, a[ks][0], a[ks][1], a[ks][2], a[ks][3],
                         __float_as_uint(bv[2*ks]), __float_as_uint(bv[2*ks + 1]));
            const int c = nt * 8 + tig * 2;
            s_h[ra * MHP + c]     = cvt_tf32(silu(d0));
            s_h[ra * MHP + c + 1] = cvt_tf32(silu(d1));
            s_h[rb * MHP + c]     = cvt_tf32(silu(d2));
            s_h[rb * MHP + c + 1] = cvt_tf32(silu(d3));
        }
    }
    __syncwarp();

    {
        uint32_t a[8][4];
        #pragma unroll
        for (int ks = 0; ks < 8; ks++) {
            a[ks][0] = hA[ra * MHP + ks * 8 + tig];
            a[ks][1] = hA[rb * MHP + ks * 8 + tig];
            a[ks][2] = hA[ra * MHP + ks * 8 + tig + 4];
            a[ks][3] = hA[rb * MHP + ks * 8 + tig + 4];
        }
        const int geA = e0 + ra, geB = e0 + rb;
        #pragma unroll
        for (int nt = 0; nt < 8; nt++) {
            const int nb = nt * 8 + gid;
            const float4* bp = (const float4*)&g_wr2t[(nb * 4 + tig) << 4];
            float4 q0 = __ldg(bp), q1 = __ldg(bp + 1), q2 = __ldg(bp + 2), q3 = __ldg(bp + 3);
            float bv[16] = {q0.x,q0.y,q0.z,q0.w, q1.x,q1.y,q1.z,q1.w,
                            q2.x,q2.y,q2.z,q2.w, q3.x,q3.y,q3.z,q3.w};
            float d0 = 0.f, d1 = 0.f, d2 = 0.f, d3 = 0.f;
            #pragma unroll
            for (int ks = 0; ks < 8; ks++)
                mma_tf32(d0, d1, d2, d3, a[ks][0], a[ks][1], a[ks][2], a[ks][3],
                         __float_as_uint(bv[2*ks]), __float_as_uint(bv[2*ks + 1]));
            const int c = nt * 8 + tig * 2;
            if (geA < E)
                *(float2*)&g_h[(size_t)geA * HH + c] =
                    make_float2(cvt_tf32(silu(d0)), cvt_tf32(silu(d1)));
            if (geB < E)
                *(float2*)&g_h[(size_t)geB * HH + c] =
                    make_float2(cvt_tf32(silu(d2)), cvt_tf32(silu(d3)));
        }
    }
}

// ---------------------------------------------------------------------------
// Fused GEMM + TP + scatter. FEPB=32, frag-order pipelined B, slice-SPLIT
// phase 1 (one m16 A cache live at a time -> ~80 regs, occ 25%).
#define FEPB 32
#define FHP  68
#define PS   712
#define FO_W    2176
#define FO_A    24960
#define FO_CUT  25472
#define FO_SRC  25504
#define FO_DST  25536
#define F_SMEM  (25568 * 4)

__global__ void __launch_bounds__(256) k_fused(
    const float* __restrict__ a0g, const float* __restrict__ a1g, const float* __restrict__ a2g,
    const float* __restrict__ cut, const int* __restrict__ ei, int E)
{
    extern __shared__ float sm[];
    float* s_h   = sm;
    float* s_w   = sm + FO_W;
    float* s_a   = sm + FO_A;
    float* s_cut = sm + FO_CUT;
    int*   s_src = (int*)(sm + FO_SRC);
    int*   s_dst = (int*)(sm + FO_DST);

    const int tid = threadIdx.x;
    const int e0  = blockIdx.x * FEPB;

    #pragma unroll
    for (int i = 0; i < 2; i++) {
        int flat = i * 256 + tid;
        int row = flat >> 4, c4 = flat & 15;
        int ge = e0 + row; if (ge >= E) ge = E - 1;
        *(float4*)&s_h[row * FHP + c4 * 4] = *(const float4*)&g_h[(size_t)ge * HH + c4 * 4];
    }
    for (int idx = tid; idx < FEPB * 13; idx += 256) {
        int e = idx / 13, k = idx - 13 * e;
        int ge = e0 + e; if (ge >= E) ge = E - 1;
        float v;
        if (k == 0)     v = a0g[ge];
        else if (k < 4) v = a1g[ge * 3 + (k - 1)];
        else            v = a2g[ge * 9 + (k - 4)];
        s_a[e * 16 + k] = v;
    }
    if (tid < FEPB) {
        int ge = e0 + tid; if (ge >= E) ge = E - 1;
        s_cut[tid] = cut[ge];
        s_src[tid] = ei[ge];
        s_dst[tid] = ei[E + ge];
    }
    __syncthreads();

    // ---- phase 1: GEMM, slice-split (one A cache live at a time) ----
    {
        const int wid = tid >> 5, lane = tid & 31;
        const int gid = lane >> 2, tig = lane & 3;
        const uint32_t* hA = (const uint32_t*)s_h;
        const int ncol = wid * 8 + gid;

        #pragma unroll
        for (int s = 0; s < 2; s++) {
            const int rA = s * 16 + gid, rB = rA + 8;
            uint32_t a[8][4];
            #pragma unroll
            for (int ks = 0; ks < 8; ks++) {
                a[ks][0] = hA[rA * FHP + ks * 8 + tig];
                a[ks][1] = hA[rB * FHP + ks * 8 + tig];
                a[ks][2] = hA[rA * FHP + ks * 8 + tig + 4];
                a[ks][3] = hA[rB * FHP + ks * 8 + tig + 4];
            }
            const float cA = s_cut[rA], cB = s_cut[rB];

            #pragma unroll
            for (int p = 0; p < NPATHS; p++) {
                const float4* __restrict__ bp =
                    (const float4*)&g_wr3t[((p * CC + ncol) * 4 + tig) << 4];
                float d0 = 0.f, d1 = 0.f, d2 = 0.f, d3 = 0.f;
                float4 q = __ldg(bp);
                #pragma unroll
                for (int half = 0; half < 4; half++) {
                    float4 qn;
                    if (half < 3) qn = __ldg(bp + half + 1);
                    const int k0 = half * 2;
                    mma_tf32(d0, d1, d2, d3,
                             a[k0][0], a[k0][1], a[k0][2], a[k0][3],
                             __float_as_uint(q.x), __float_as_uint(q.y));
                    mma_tf32(d0, d1, d2, d3,
                             a[k0+1][0], a[k0+1][1], a[k0+1][2], a[k0+1][3],
                             __float_as_uint(q.z), __float_as_uint(q.w));
                    q = qn;
                }
                const int c = p * 64 + wid * 8 + tig * 2;
                *(float2*)&s_w[rA * PS + c] = make_float2(d0 * cA, d1 * cA);
                *(float2*)&s_w[rB * PS + c] = make_float2(d2 * cB, d3 * cB);
            }
        }
    }
    __syncthreads();

    // ---- phase 2: tensor product + scatter, 2 edges per thread ----
    #pragma unroll
    for (int el = 0; el < 2; el++) {
        const int e  = (tid >> 4) + el * 16;
        const int c0 = (tid & 15) * 4;
        const int ge = e0 + e;
        if (ge >= E) continue;
        const int src = s_src[e];
        const int dst = s_dst[e];

        const float* __restrict__ up = &g_u[src * NCOMP * CC + c0];
        float s0[4], s1[3][4], s2[9][4];
        *(float4*)s0 = __ldg((const float4*)&up[0]);
        #pragma unroll
        for (int i = 0; i < 3; i++) *(float4*)s1[i] = __ldg((const float4*)&up[(1 + i) * CC]);
        #pragma unroll
        for (int q = 0; q < 9; q++) *(float4*)s2[q] = __ldg((const float4*)&up[(4 + q) * CC]);

        float av[13];
        #pragma unroll
        for (int k = 0; k < 13; k++) av[k] = s_a[e * 16 + k];
        const float  a0v = av[0];
        const float* a1v = av + 1;
        const float* a2v = av + 4;

        float w[NPATHS][4];
        #pragma unroll
        for (int p = 0; p < NPATHS; p++)
            *(float4*)w[p] = *(const float4*)&s_w[e * PS + p * CC + c0];

        float* __restrict__ ap = &g_acc[dst * NCOMP * CC + c0];

        float o0[4];
        #pragma unroll
        for (int c = 0; c < 4; c++) {
            float dot11 = a1v[0]*s1[0][c] + a1v[1]*s1[1][c] + a1v[2]*s1[2][c];
            float dot22 = 0.f;
            #pragma unroll
            for (int q = 0; q < 9; q++) dot22 = fmaf(a2v[q], s2[q][c], dot22);
            o0[c] = w[0][c] * (a0v * s0[c]) + w[1][c] * dot11 + w[2][c] * dot22;
        }
        red4(ap, o0[0], o0[1], o0[2], o0[3]);

        #pragma unroll
        for (int i = 0; i < 3; i++) {
            float o1[4];
            #pragma unroll
            for (int c = 0; c < 4; c++) {
                float m21 = 0.f, m12 = 0.f;
                #pragma unroll
                for (int j = 0; j < 3; j++) {
                    m21 = fmaf(a2v[i*3 + j], s1[j][c], m21);
                    m12 = fmaf(a1v[j], s2[i*3 + j][c], m12);
                }
                o1[c] = w[3][c]*(a1v[i]*s0[c]) + w[4][c]*(a0v*s1[i][c]) + w[5][c]*m21 + w[6][c]*m12;
            }
            red4(ap + (1 + i) * CC, o1[0], o1[1], o1[2], o1[3]);
        }

        #pragma unroll
        for (int i = 0; i < 3; i++) {
            #pragma unroll
            for (int j = 0; j < 3; j++) {
                float o2[4];
                #pragma unroll
                for (int c = 0; c < 4; c++) {
                    float mm = 0.f;
                    #pragma unroll
                    for (int kk = 0; kk < 3; kk++)
                        mm = fmaf(a2v[i*3 + kk], s2[kk*3 + j][c], mm);
                    o2[c] = w[7][c]*(a1v[i]*s1[j][c]) + w[8][c]*(a2v[i*3+j]*s0[c])
                          + w[9][c]*(a0v*s2[i*3+j][c]) + w[10][c]*mm;
                }
                red4(ap + (4 + i*3 + j) * CC, o2[0], o2[1], o2[2], o2[3]);
            }
        }
    }
}

// ---------------------------------------------------------------------------
__global__ void k_final(const float* __restrict__ D0, const float* __restrict__ D1,
                        const float* __restrict__ D2, float* __restrict__ out, int N)
{
    int idx = blockIdx.x * blockDim.x + threadIdx.x;
    if (idx >= N * CC) return;
    const int n = idx >> 6, c = idx & 63;
    const float inv = 1.0f / 32.0f;
    const float* __restrict__ ap = &g_acc[n * NCOMP * CC + c];

    float m0 = ap[0] * inv;
    float m1[3], m2[9];
    #pragma unroll
    for (int i = 0; i < 3; i++) m1[i] = ap[(1 + i) * CC] * inv;
    #pragma unroll
    for (int q = 0; q < 9; q++) m2[q] = ap[(4 + q) * CC] * inv;

    out[idx] = m0 * __ldg(&D0[0]);

    float* __restrict__ o1 = out + N * CC;
    #pragma unroll
    for (int j = 0; j < 3; j++) {
        float s = 0.f;
        #pragma unroll
        for (int i = 0; i < 3; i++) s = fmaf(m1[i], __ldg(&D1[i * 3 + j]), s);
        o1[idx * 3 + j] = s;
    }
    float* __restrict__ o2 = out + N * CC * 4;
    #pragma unroll
    for (int q = 0; q < 9; q++) {
        float s = 0.f;
        #pragma unroll
        for (int p = 0; p < 9; p++) s = fmaf(m2[p], __ldg(&D2[p * 9 + q]), s);
        o2[idx * 9 + q] = s;
    }
}

// ---------------------------------------------------------------------------
extern "C" void kernel_launch(void* const* d_in, const int* in_sizes, int n_in,
                              void* d_out, int out_size)
{
    const float* t0  = (const float*)d_in[0];
    const float* t1  = (const float*)d_in[1];
    const float* t2  = (const float*)d_in[2];
    const float* a0  = (const float*)d_in[3];
    const float* a1  = (const float*)d_in[4];
    const float* a2  = (const float*)d_in[5];
    const float* ef  = (const float*)d_in[6];
    const float* cut = (const float*)d_in[7];
    const float* W0  = (const float*)d_in[8];
    const float* W1  = (const float*)d_in[9];
    const float* W2  = (const float*)d_in[10];
    const float* Wr0 = (const float*)d_in[11];
    const float* Wr1 = (const float*)d_in[12];
    const float* Wr2 = (const float*)d_in[13];
    const float* Wr3 = (const float*)d_in[14];
    const float* D0  = (const float*)d_in[15];
    const float* D1  = (const float*)d_in[16];
    const float* D2  = (const float*)d_in[17];
    const int*   ei  = (const int*)d_in[18];

    const int N = in_sizes[0] / CC;   // 8000
    const int E = in_sizes[3];        // 256000
    float* out = (float*)d_out;

    cudaFuncSetAttribute(k_mlp,   cudaFuncAttributeMaxDynamicSharedMemorySize, M_SMEM);
    cudaFuncSetAttribute(k_fused, cudaFuncAttributeMaxDynamicSharedMemorySize, F_SMEM);

    const int n4 = (N * NCOMP * CC) / 4;
    k_prep<<<(n4 + 255) / 256, 256>>>(Wr0, Wr1, Wr2, Wr3, n4);
    k_linear_up<<<N, 128>>>(t0, t1, t2, W0, W1, W2);
    k_mlp<<<(E + MEPB - 1) / MEPB, 256, M_SMEM>>>(ef, E);
    k_fused<<<(E + FEPB - 1) / FEPB, 256, F_SMEM>>>(a0, a1, a2, cut, ei, E);
    k_final<<<(N * CC + 255) / 256, 256>>>(D0, D1, D2, out, N);
}

// round 16
// speedup vs baseline: 1.1774x; 1.1774x over previous
#include <cuda_runtime.h>
#include <cstdint>

#define CC     64
#define NCOMP  13
#define NPATHS 11
#define RR     8
#define HH     64
#define MAXN   8000
#define MAXE   256000
#define WCOLS  (NPATHS * CC)   // 704

__device__ __align__(16) float g_u[MAXN * NCOMP * CC];
__device__ __align__(16) float g_acc[MAXN * NCOMP * CC];
__device__ __align__(16) float g_h[MAXE * HH];
// fragment-order tf32 weights: [(col*4 + tig)*16 + ks*2 + {b0,b1}]
__device__ __align__(16) float g_wr3t[WCOLS * 4 * 16];
__device__ __align__(16) float g_wr0t[HH * 4 * 2];
__device__ __align__(16) float g_wr1t[HH * 4 * 16];
__device__ __align__(16) float g_wr2t[HH * 4 * 16];

typedef unsigned long long u64t;

__device__ __forceinline__ u64t pack2(float lo, float hi) {
    u64t r; asm("mov.b64 %0,{%1,%2};" : "=l"(r) : "f"(lo), "f"(hi)); return r;
}
__device__ __forceinline__ void unpack2(u64t v, float& lo, float& hi) {
    asm("mov.b64 {%0,%1},%2;" : "=f"(lo), "=f"(hi) : "l"(v));
}
__device__ __forceinline__ u64t fma2(u64t a, u64t b, u64t c) {
    u64t d; asm("fma.rn.f32x2 %0,%1,%2,%3;" : "=l"(d) : "l"(a), "l"(b), "l"(c)); return d;
}
__device__ __forceinline__ void red4(float* p, float x, float y, float z, float w) {
    asm volatile("red.global.add.v4.f32 [%0], {%1,%2,%3,%4};"
                 :: "l"(p), "f"(x), "f"(y), "f"(z), "f"(w) : "memory");
}
__device__ __forceinline__ float silu(float x) { return x / (1.0f + __expf(-x)); }
__device__ __forceinline__ float cvt_tf32(float x) {
    uint32_t u; asm("cvt.rna.tf32.f32 %0, %1;" : "=r"(u) : "f"(x));
    return __uint_as_float(u);
}
__device__ __forceinline__ void mma_tf32(float& d0, float& d1, float& d2, float& d3,
                                         uint32_t a0, uint32_t a1, uint32_t a2, uint32_t a3,
                                         uint32_t b0, uint32_t b1) {
    asm volatile("mma.sync.aligned.m16n8k8.row.col.f32.tf32.tf32.f32 "
                 "{%0,%1,%2,%3}, {%4,%5,%6,%7}, {%8,%9}, {%0,%1,%2,%3};"
                 : "+f"(d0), "+f"(d1), "+f"(d2), "+f"(d3)
                 : "r"(a0), "r"(a1), "r"(a2), "r"(a3), "r"(b0), "r"(b1));
}

// ---------------------------------------------------------------------------
__global__ void k_prep(const float* __restrict__ Wr0, const float* __restrict__ Wr1,
                       const float* __restrict__ Wr2, const float* __restrict__ Wr3,
                       int n4) {
    int i = blockIdx.x * blockDim.x + threadIdx.x;
    if (i < n4) reinterpret_cast<float4*>(g_acc)[i] = make_float4(0.f, 0.f, 0.f, 0.f);
    if (i < 22528) {
        int c = i >> 5, t = (i >> 3) & 3, ks = i & 7;
        g_wr3t[((c * 4 + t) << 4) + ks * 2]     = cvt_tf32(Wr3[(ks * 8 + t) * WCOLS + c]);
        g_wr3t[((c * 4 + t) << 4) + ks * 2 + 1] = cvt_tf32(Wr3[(ks * 8 + t + 4) * WCOLS + c]);
    } else if (i < 22528 + 2048) {
        int j = i - 22528;
        int c = j >> 5, t = (j >> 3) & 3, ks = j & 7;
        g_wr1t[((c * 4 + t) << 4) + ks * 2]     = cvt_tf32(Wr1[(ks * 8 + t) * HH + c]);
        g_wr1t[((c * 4 + t) << 4) + ks * 2 + 1] = cvt_tf32(Wr1[(ks * 8 + t + 4) * HH + c]);
    } else if (i < 22528 + 4096) {
        int j = i - 22528 - 2048;
        int c = j >> 5, t = (j >> 3) & 3, ks = j & 7;
        g_wr2t[((c * 4 + t) << 4) + ks * 2]     = cvt_tf32(Wr2[(ks * 8 + t) * HH + c]);
        g_wr2t[((c * 4 + t) << 4) + ks * 2 + 1] = cvt_tf32(Wr2[(ks * 8 + t + 4) * HH + c]);
    } else if (i < 22528 + 4096 + 256) {
        int j = i - 22528 - 4096;
        int c = j >> 2, t = j & 3;
        g_wr0t[j * 2]     = cvt_tf32(Wr0[t * HH + c]);
        g_wr0t[j * 2 + 1] = cvt_tf32(Wr0[(t + 4) * HH + c]);
    }
}

// ---------------------------------------------------------------------------
__global__ void __launch_bounds__(128) k_linear_up(
    const float* __restrict__ t0, const float* __restrict__ t1, const float* __restrict__ t2,
    const float* __restrict__ W0, const float* __restrict__ W1, const float* __restrict__ W2)
{
    __shared__ float s_t[NCOMP][CC];
    const int n = blockIdx.x, tid = threadIdx.x;
    for (int idx = tid; idx < NCOMP * CC; idx += 128) {
        int comp = idx >> 6, c = idx & 63;
        float v;
        if (comp == 0)      v = t0[n * CC + c];
        else if (comp < 4)  v = t1[(n * CC + c) * 3 + (comp - 1)];
        else                v = t2[(n * CC + c) * 9 + (comp - 4)];
        s_t[comp][c] = v;
    }
    __syncthreads();
    for (int pr = tid; pr < NCOMP * 32; pr += 128) {
        int comp = pr >> 5, dp = (pr & 31) * 2;
        const float* __restrict__ W = (comp == 0) ? W0 : ((comp < 4) ? W1 : W2);
        u64t acc = 0ull;
        #pragma unroll 8
        for (int c = 0; c < CC; c++) {
            float s = s_t[comp][c];
            acc = fma2(*(const u64t*)&W[c * CC + dp], pack2(s, s), acc);
        }
        float lo, hi; unpack2(acc, lo, hi);
        float* o = &g_u[(n * NCOMP + comp) * CC + dp];
        o[0] = lo; o[1] = hi;
    }
}

// ---------------------------------------------------------------------------
// Tensor-core radial MLP (unchanged from round 11)
#define MEPB 128
#define MHP  68
#define M_SMEM ((1024 + MEPB * MHP) * 4)

__global__ void __launch_bounds__(256, 4) k_mlp(const float* __restrict__ ef, int E)
{
    extern __shared__ float sm[];
    float* s_f = sm;
    float* s_h = sm + 1024;

    const int tid  = threadIdx.x;
    const int e0   = blockIdx.x * MEPB;
    const int lane = tid & 31;
    const int wid  = tid >> 5;
    const int gid  = lane >> 2, tig = lane & 3;
    const int ra   = wid * 16 + gid, rb = ra + 8;

    {
        int row = tid >> 1, q = (tid & 1) * 4;
        int ge = e0 + row; if (ge >= E) ge = E - 1;
        float4 v = *(const float4*)&ef[ge * RR + q];
        v.x = cvt_tf32(v.x); v.y = cvt_tf32(v.y); v.z = cvt_tf32(v.z); v.w = cvt_tf32(v.w);
        *(float4*)&s_f[row * RR + q] = v;
    }
    __syncwarp();

    const uint32_t* fA = (const uint32_t*)s_f;
    const uint32_t* hA = (const uint32_t*)s_h;

    {
        uint32_t a0 = fA[ra * RR + tig], a1 = fA[rb * RR + tig];
        uint32_t a2 = fA[ra * RR + tig + 4], a3 = fA[rb * RR + tig + 4];
        #pragma unroll
        for (int nt = 0; nt < 8; nt++) {
            const int nb = nt * 8 + gid;
            float2 b = *(const float2*)&g_wr0t[(nb * 4 + tig) * 2];
            float d0 = 0.f, d1 = 0.f, d2 = 0.f, d3 = 0.f;
            mma_tf32(d0, d1, d2, d3, a0, a1, a2, a3,
                     __float_as_uint(b.x), __float_as_uint(b.y));
            const int c = nt * 8 + tig * 2;
            s_h[ra * MHP + c]     = cvt_tf32(silu(d0));
            s_h[ra * MHP + c + 1] = cvt_tf32(silu(d1));
            s_h[rb * MHP + c]     = cvt_tf32(silu(d2));
            s_h[rb * MHP + c + 1] = cvt_tf32(silu(d3));
        }
    }
    __syncwarp();

    {
        uint32_t a[8][4];
        #pragma unroll
        for (int ks = 0; ks < 8; ks++) {
            a[ks][0] = hA[ra * MHP + ks * 8 + tig];
            a[ks][1] = hA[rb * MHP + ks * 8 + tig];
            a[ks][2] = hA[ra * MHP + ks * 8 + tig + 4];
            a[ks][3] = hA[rb * MHP + ks * 8 + tig + 4];
        }
        __syncwarp();
        #pragma unroll
        for (int nt = 0; nt < 8; nt++) {
            const int nb = nt * 8 + gid;
            const float4* bp = (const float4*)&g_wr1t[(nb * 4 + tig) << 4];
            float4 q0 = __ldg(bp), q1 = __ldg(bp + 1), q2 = __ldg(bp + 2), q3 = __ldg(bp + 3);
            float bv[16] = {q0.x,q0.y,q0.z,q0.w, q1.x,q1.y,q1.z,q1.w,
                            q2.x,q2.y,q2.z,q2.w, q3.x,q3.y,q3.z,q3.w};
            float d0 = 0.f, d1 = 0.f, d2 = 0.f, d3 = 0.f;
            #pragma unroll
            for (int ks = 0; ks < 8; ks++)
                mma_tf32(d0, d1, d2, d3, a[ks][0], a[ks][1], a[ks][2], a[ks][3],
                         __float_as_uint(bv[2*ks]), __float_as_uint(bv[2*ks + 1]));
            const int c = nt * 8 + tig * 2;
            s_h[ra * MHP + c]     = cvt_tf32(silu(d0));
            s_h[ra * MHP + c + 1] = cvt_tf32(silu(d1));
            s_h[rb * MHP + c]     = cvt_tf32(silu(d2));
            s_h[rb * MHP + c + 1] = cvt_tf32(silu(d3));
        }
    }
    __syncwarp();

    {
        uint32_t a[8][4];
        #pragma unroll
        for (int ks = 0; ks < 8; ks++) {
            a[ks][0] = hA[ra * MHP + ks * 8 + tig];
            a[ks][1] = hA[rb * MHP + ks * 8 + tig];
            a[ks][2] = hA[ra * MHP + ks * 8 + tig + 4];
            a[ks][3] = hA[rb * MHP + ks * 8 + tig + 4];
        }
        const int geA = e0 + ra, geB = e0 + rb;
        #pragma unroll
        for (int nt = 0; nt < 8; nt++) {
            const int nb = nt * 8 + gid;
            const float4* bp = (const float4*)&g_wr2t[(nb * 4 + tig) << 4];
            float4 q0 = __ldg(bp), q1 = __ldg(bp + 1), q2 = __ldg(bp + 2), q3 = __ldg(bp + 3);
            float bv[16] = {q0.x,q0.y,q0.z,q0.w, q1.x,q1.y,q1.z,q1.w,
                            q2.x,q2.y,q2.z,q2.w, q3.x,q3.y,q3.z,q3.w};
            float d0 = 0.f, d1 = 0.f, d2 = 0.f, d3 = 0.f;
            #pragma unroll
            for (int ks = 0; ks < 8; ks++)
                mma_tf32(d0, d1, d2, d3, a[ks][0], a[ks][1], a[ks][2], a[ks][3],
                         __float_as_uint(bv[2*ks]), __float_as_uint(bv[2*ks + 1]));
            const int c = nt * 8 + tig * 2;
            if (geA < E)
                *(float2*)&g_h[(size_t)geA * HH + c] =
                    make_float2(cvt_tf32(silu(d0)), cvt_tf32(silu(d1)));
            if (geB < E)
                *(float2*)&g_h[(size_t)geB * HH + c] =
                    make_float2(cvt_tf32(silu(d2)), cvt_tf32(silu(d3)));
        }
    }
}

// ---------------------------------------------------------------------------
// Fused GEMM + TP + scatter. Round-13 body (FEPB=32, merged slices, frag-order
// pipelined B) + HARD 128-reg cap via __launch_bounds__(256, 2) -> 2 blocks/SM.
#define FEPB 32
#define FHP  68
#define PS   712
#define FO_W    2176
#define FO_A    24960
#define FO_CUT  25472
#define FO_SRC  25504
#define FO_DST  25536
#define F_SMEM  (25568 * 4)

__global__ void __launch_bounds__(256, 2) k_fused(
    const float* __restrict__ a0g, const float* __restrict__ a1g, const float* __restrict__ a2g,
    const float* __restrict__ cut, const int* __restrict__ ei, int E)
{
    extern __shared__ float sm[];
    float* s_h   = sm;
    float* s_w   = sm + FO_W;
    float* s_a   = sm + FO_A;
    float* s_cut = sm + FO_CUT;
    int*   s_src = (int*)(sm + FO_SRC);
    int*   s_dst = (int*)(sm + FO_DST);

    const int tid = threadIdx.x;
    const int e0  = blockIdx.x * FEPB;

    #pragma unroll
    for (int i = 0; i < 2; i++) {
        int flat = i * 256 + tid;
        int row = flat >> 4, c4 = flat & 15;
        int ge = e0 + row; if (ge >= E) ge = E - 1;
        *(float4*)&s_h[row * FHP + c4 * 4] = *(const float4*)&g_h[(size_t)ge * HH + c4 * 4];
    }
    for (int idx = tid; idx < FEPB * 13; idx += 256) {
        int e = idx / 13, k = idx - 13 * e;
        int ge = e0 + e; if (ge >= E) ge = E - 1;
        float v;
        if (k == 0)     v = a0g[ge];
        else if (k < 4) v = a1g[ge * 3 + (k - 1)];
        else            v = a2g[ge * 9 + (k - 4)];
        s_a[e * 16 + k] = v;
    }
    if (tid < FEPB) {
        int ge = e0 + tid; if (ge >= E) ge = E - 1;
        s_cut[tid] = cut[ge];
        s_src[tid] = ei[ge];
        s_dst[tid] = ei[E + ge];
    }
    __syncthreads();

    // ---- phase 1: GEMM, two m16 slices per warp share pipelined B frags ----
    {
        const int wid = tid >> 5, lane = tid & 31;
        const int gid = lane >> 2, tig = lane & 3;

        uint32_t a[2][8][4];
        const uint32_t* hA = (const uint32_t*)s_h;
        #pragma unroll
        for (int s = 0; s < 2; s++) {
            const int rA = s * 16 + gid, rB = rA + 8;
            #pragma unroll
            for (int ks = 0; ks < 8; ks++) {
                a[s][ks][0] = hA[rA * FHP + ks * 8 + tig];
                a[s][ks][1] = hA[rB * FHP + ks * 8 + tig];
                a[s][ks][2] = hA[rA * FHP + ks * 8 + tig + 4];
                a[s][ks][3] = hA[rB * FHP + ks * 8 + tig + 4];
            }
        }
        const float cA0 = s_cut[gid],      cB0 = s_cut[gid + 8];
        const float cA1 = s_cut[gid + 16], cB1 = s_cut[gid + 24];
        const int ncol = wid * 8 + gid;

        #pragma unroll
        for (int p = 0; p < NPATHS; p++) {
            const float4* __restrict__ bp =
                (const float4*)&g_wr3t[(((p * CC + ncol) * 4 + tig)) << 4];
            float d0[4] = {0.f, 0.f, 0.f, 0.f};
            float d1[4] = {0.f, 0.f, 0.f, 0.f};
            float4 q = __ldg(bp);
            #pragma unroll
            for (int half = 0; half < 4; half++) {
                float4 qn;
                if (half < 3) qn = __ldg(bp + half + 1);
                uint32_t b0 = __float_as_uint(q.x), b1 = __float_as_uint(q.y);
                const int k0 = half * 2;
                mma_tf32(d0[0], d0[1], d0[2], d0[3],
                         a[0][k0][0], a[0][k0][1], a[0][k0][2], a[0][k0][3], b0, b1);
                mma_tf32(d1[0], d1[1], d1[2], d1[3],
                         a[1][k0][0], a[1][k0][1], a[1][k0][2], a[1][k0][3], b0, b1);
                b0 = __float_as_uint(q.z); b1 = __float_as_uint(q.w);
                mma_tf32(d0[0], d0[1], d0[2], d0[3],
                         a[0][k0+1][0], a[0][k0+1][1], a[0][k0+1][2], a[0][k0+1][3], b0, b1);
                mma_tf32(d1[0], d1[1], d1[2], d1[3],
                         a[1][k0+1][0], a[1][k0+1][1], a[1][k0+1][2], a[1][k0+1][3], b0, b1);
                q = qn;
            }
            const int c = p * 64 + wid * 8 + tig * 2;
            *(float2*)&s_w[gid * PS + c]        = make_float2(d0[0] * cA0, d0[1] * cA0);
            *(float2*)&s_w[(gid + 8) * PS + c]  = make_float2(d0[2] * cB0, d0[3] * cB0);
            *(float2*)&s_w[(gid + 16) * PS + c] = make_float2(d1[0] * cA1, d1[1] * cA1);
            *(float2*)&s_w[(gid + 24) * PS + c] = make_float2(d1[2] * cB1, d1[3] * cB1);
        }
    }
    __syncthreads();

    // ---- phase 2: tensor product + scatter, 2 edges per thread ----
    #pragma unroll
    for (int el = 0; el < 2; el++) {
        const int e  = (tid >> 4) + el * 16;
        const int c0 = (tid & 15) * 4;
        const int ge = e0 + e;
        if (ge >= E) continue;
        const int src = s_src[e];
        const int dst = s_dst[e];

        const float* __restrict__ up = &g_u[src * NCOMP * CC + c0];
        float s0[4], s1[3][4], s2[9][4];
        *(float4*)s0 = __ldg((const float4*)&up[0]);
        #pragma unroll
        for (int i = 0; i < 3; i++) *(float4*)s1[i] = __ldg((const float4*)&up[(1 + i) * CC]);
        #pragma unroll
        for (int q = 0; q < 9; q++) *(float4*)s2[q] = __ldg((const float4*)&up[(4 + q) * CC]);

        float av[13];
        #pragma unroll
        for (int k = 0; k < 13; k++) av[k] = s_a[e * 16 + k];
        const float  a0v = av[0];
        const float* a1v = av + 1;
        const float* a2v = av + 4;

        float w[NPATHS][4];
        #pragma unroll
        for (int p = 0; p < NPATHS; p++)
            *(float4*)w[p] = *(const float4*)&s_w[e * PS + p * CC + c0];

        float* __restrict__ ap = &g_acc[dst * NCOMP * CC + c0];

        float o0[4];
        #pragma unroll
        for (int c = 0; c < 4; c++) {
            float dot11 = a1v[0]*s1[0][c] + a1v[1]*s1[1][c] + a1v[2]*s1[2][c];
            float dot22 = 0.f;
            #pragma unroll
            for (int q = 0; q < 9; q++) dot22 = fmaf(a2v[q], s2[q][c], dot22);
            o0[c] = w[0][c] * (a0v * s0[c]) + w[1][c] * dot11 + w[2][c] * dot22;
        }
        red4(ap, o0[0], o0[1], o0[2], o0[3]);

        #pragma unroll
        for (int i = 0; i < 3; i++) {
            float o1[4];
            #pragma unroll
            for (int c = 0; c < 4; c++) {
                float m21 = 0.f, m12 = 0.f;
                #pragma unroll
                for (int j = 0; j < 3; j++) {
                    m21 = fmaf(a2v[i*3 + j], s1[j][c], m21);
                    m12 = fmaf(a1v[j], s2[i*3 + j][c], m12);
                }
                o1[c] = w[3][c]*(a1v[i]*s0[c]) + w[4][c]*(a0v*s1[i][c]) + w[5][c]*m21 + w[6][c]*m12;
            }
            red4(ap + (1 + i) * CC, o1[0], o1[1], o1[2], o1[3]);
        }

        #pragma unroll
        for (int i = 0; i < 3; i++) {
            #pragma unroll
            for (int j = 0; j < 3; j++) {
                float o2[4];
                #pragma unroll
                for (int c = 0; c < 4; c++) {
                    float mm = 0.f;
                    #pragma unroll
                    for (int kk = 0; kk < 3; kk++)
                        mm = fmaf(a2v[i*3 + kk], s2[kk*3 + j][c], mm);
                    o2[c] = w[7][c]*(a1v[i]*s1[j][c]) + w[8][c]*(a2v[i*3+j]*s0[c])
                          + w[9][c]*(a0v*s2[i*3+j][c]) + w[10][c]*mm;
                }
                red4(ap + (4 + i*3 + j) * CC, o2[0], o2[1], o2[2], o2[3]);
            }
        }
    }
}

// ---------------------------------------------------------------------------
__global__ void k_final(const float* __restrict__ D0, const float* __restrict__ D1,
                        const float* __restrict__ D2, float* __restrict__ out, int N)
{
    int idx = blockIdx.x * blockDim.x + threadIdx.x;
    if (idx >= N * CC) return;
    const int n = idx >> 6, c = idx & 63;
    const float inv = 1.0f / 32.0f;
    const float* __restrict__ ap = &g_acc[n * NCOMP * CC + c];

    float m0 = ap[0] * inv;
    float m1[3], m2[9];
    #pragma unroll
    for (int i = 0; i < 3; i++) m1[i] = ap[(1 + i) * CC] * inv;
    #pragma unroll
    for (int q = 0; q < 9; q++) m2[q] = ap[(4 + q) * CC] * inv;

    out[idx] = m0 * __ldg(&D0[0]);

    float* __restrict__ o1 = out + N * CC;
    #pragma unroll
    for (int j = 0; j < 3; j++) {
        float s = 0.f;
        #pragma unroll
        for (int i = 0; i < 3; i++) s = fmaf(m1[i], __ldg(&D1[i * 3 + j]), s);
        o1[idx * 3 + j] = s;
    }
    float* __restrict__ o2 = out + N * CC * 4;
    #pragma unroll
    for (int q = 0; q < 9; q++) {
        float s = 0.f;
        #pragma unroll
        for (int p = 0; p < 9; p++) s = fmaf(m2[p], __ldg(&D2[p * 9 + q]), s);
        o2[idx * 9 + q] = s;
    }
}

// ---------------------------------------------------------------------------
extern "C" void kernel_launch(void* const* d_in, const int* in_sizes, int n_in,
                              void* d_out, int out_size)
{
    const float* t0  = (const float*)d_in[0];
    const float* t1  = (const float*)d_in[1];
    const float* t2  = (const float*)d_in[2];
    const float* a0  = (const float*)d_in[3];
    const float* a1  = (const float*)d_in[4];
    const float* a2  = (const float*)d_in[5];
    const float* ef  = (const float*)d_in[6];
    const float* cut = (const float*)d_in[7];
    const float* W0  = (const float*)d_in[8];
    const float* W1  = (const float*)d_in[9];
    const float* W2  = (const float*)d_in[10];
    const float* Wr0 = (const float*)d_in[11];
    const float* Wr1 = (const float*)d_in[12];
    const float* Wr2 = (const float*)d_in[13];
    const float* Wr3 = (const float*)d_in[14];
    const float* D0  = (const float*)d_in[15];
    const float* D1  = (const float*)d_in[16];
    const float* D2  = (const float*)d_in[17];
    const int*   ei  = (const int*)d_in[18];

    const int N = in_sizes[0] / CC;   // 8000
    const int E = in_sizes[3];        // 256000
    float* out = (float*)d_out;

    cudaFuncSetAttribute(k_mlp,   cudaFuncAttributeMaxDynamicSharedMemorySize, M_SMEM);
    cudaFuncSetAttribute(k_fused, cudaFuncAttributeMaxDynamicSharedMemorySize, F_SMEM);

    const int n4 = (N * NCOMP * CC) / 4;
    k_prep<<<(n4 + 255) / 256, 256>>>(Wr0, Wr1, Wr2, Wr3, n4);
    k_linear_up<<<N, 128>>>(t0, t1, t2, W0, W1, W2);
    k_mlp<<<(E + MEPB - 1) / MEPB, 256, M_SMEM>>>(ef, E);
    k_fused<<<(E + FEPB - 1) / FEPB, 256, F_SMEM>>>(a0, a1, a2, cut, ei, E);
    k_final<<<(N * CC + 255) / 256, 256>>>(D0, D1, D2, out, N);
}